// round 4
// baseline (speedup 1.0000x reference)
#include <cuda_runtime.h>
#include <cuda_bf16.h>
#include <cstdint>

#define NN 50000
#define KD 128
#define EMAX 1000000

// ---------------- scratch (device globals; no allocation allowed) ----------
__device__ int   g_outdeg[NN];
__device__ int   g_indeg[NN];
__device__ float g_norm_src[NN];
__device__ float g_norm_dst[NN];
__device__ int   g_off[NN + 1];
__device__ int   g_cursor[NN];
__device__ int   g_chunk_sum[256];
__device__ int   g_csrc[EMAX];
__device__ __nv_bfloat16 g_ya[(size_t)NN * 128];
__device__ __nv_bfloat16 g_yb[(size_t)NN * 128];
__device__ float g_h[(size_t)NN * 128];

// ---------------- f32x2 packed-FMA helpers (Blackwell) ----------------------
__device__ __forceinline__ unsigned long long pk2(float x) {
    unsigned long long r;
    asm("mov.b64 %0, {%1, %1};" : "=l"(r) : "f"(x));
    return r;
}
__device__ __forceinline__ void fma2(unsigned long long& acc, unsigned long long a,
                                     unsigned long long b) {
    asm("fma.rn.f32x2 %0, %1, %2, %0;" : "+l"(acc) : "l"(a), "l"(b));
}
__device__ __forceinline__ float2 up2(unsigned long long v) {
    float2 f;
    asm("mov.b64 {%0, %1}, %2;" : "=f"(f.x), "=f"(f.y) : "l"(v));
    return f;
}

// ---------------- tiny kernels ----------------------------------------------
__global__ void zero_int2(int* a, int* b, int n) {
    int i = blockIdx.x * blockDim.x + threadIdx.x;
    if (i < n) { a[i] = 0; b[i] = 0; }
}

__global__ void deg_kernel(const int* __restrict__ src, const int* __restrict__ dst, int E) {
    int i = blockIdx.x * blockDim.x + threadIdx.x;
    if (i < E) {
        atomicAdd(&g_outdeg[src[i]], 1);
        atomicAdd(&g_indeg[dst[i]], 1);
    }
}

__global__ void scan_sum_kernel() {
    __shared__ int s[256];
    int t = threadIdx.x;
    int idx = blockIdx.x * 256 + t;
    int v = (idx < NN) ? g_indeg[idx] : 0;
    s[t] = v; __syncthreads();
    for (int o = 128; o > 0; o >>= 1) {
        if (t < o) s[t] += s[t + o];
        __syncthreads();
    }
    if (t == 0) g_chunk_sum[blockIdx.x] = s[0];
}

__global__ void scan_apply_kernel(int nchunk, int E) {
    __shared__ int cs[256];
    __shared__ int s[256];
    int t = threadIdx.x;
    int cv = (t < nchunk) ? g_chunk_sum[t] : 0;
    cs[t] = cv; __syncthreads();
    for (int o = 1; o < 256; o <<= 1) {
        int x = (t >= o) ? cs[t - o] : 0;
        __syncthreads();
        cs[t] += x;
        __syncthreads();
    }
    int base = (blockIdx.x == 0) ? 0 : cs[blockIdx.x - 1];

    int idx = blockIdx.x * 256 + t;
    int v = (idx < NN) ? g_indeg[idx] : 0;
    s[t] = v; __syncthreads();
    for (int o = 1; o < 256; o <<= 1) {
        int x = (t >= o) ? s[t - o] : 0;
        __syncthreads();
        s[t] += x;
        __syncthreads();
    }
    if (idx < NN) {
        int excl = base + s[t] - v;
        g_off[idx] = excl;
        g_cursor[idx] = excl;
        g_norm_src[idx] = rsqrtf(fmaxf((float)g_outdeg[idx], 1.0f));
        g_norm_dst[idx] = rsqrtf(fmaxf((float)v, 1.0f));
    }
    if (idx == 0) g_off[NN] = E;
}

__global__ void fill_kernel(const int* __restrict__ src, const int* __restrict__ dst, int E) {
    int e = blockIdx.x * blockDim.x + threadIdx.x;
    if (e < E) {
        int pos = atomicAdd(&g_cursor[dst[e]], 1);
        g_csrc[pos] = src[e];
    }
}

// ---------------- GEMM: Y[i,:] = [ns[i]] * (X[i,:] @ W)  -> bf16 Y ----------
template <int D, bool SCALE>
__global__ void __launch_bounds__(256)
gemm_kernel(const float* __restrict__ X, const float* __restrict__ W,
            const float* __restrict__ scale, __nv_bfloat16* __restrict__ Y, int n) {
    constexpr int BM = 64;
    constexpr int BK = 32;
    constexpr int TM = 4;
    constexpr int TN = (BM * D) / (256 * TM);
    constexpr int NP = TN / 2;

    __shared__ float Xs[BM][BK + 4];
    __shared__ float Ws[BK][D];

    const int tid  = threadIdx.x;
    const int row0 = blockIdx.x * BM;
    const int tr   = tid / 16;
    const int tc   = tid % 16;

    unsigned long long acc[TM][NP];
#pragma unroll
    for (int m = 0; m < TM; m++)
#pragma unroll
        for (int p = 0; p < NP; p++) acc[m][p] = 0ull;

    for (int k0 = 0; k0 < KD; k0 += BK) {
#pragma unroll
        for (int i = 0; i < 2; i++) {
            int lin = tid + i * 256;
            int r  = lin >> 3;
            int kq = lin & 7;
            float4 v = make_float4(0.f, 0.f, 0.f, 0.f);
            int gr = row0 + r;
            if (gr < n)
                v = *(const float4*)(X + (size_t)gr * KD + k0 + kq * 4);
            Xs[r][kq * 4 + 0] = v.x;
            Xs[r][kq * 4 + 1] = v.y;
            Xs[r][kq * 4 + 2] = v.z;
            Xs[r][kq * 4 + 3] = v.w;
        }
        constexpr int WL = (BK * D) / (4 * 256);
#pragma unroll
        for (int i = 0; i < WL; i++) {
            int lin = tid + i * 256;
            int k  = lin / (D / 4);
            int cq = lin % (D / 4);
            *(float4*)&Ws[k][cq * 4] = *(const float4*)(W + (size_t)(k0 + k) * D + cq * 4);
        }
        __syncthreads();

#pragma unroll
        for (int kk = 0; kk < BK; kk++) {
            unsigned long long a2[TM], b2[NP];
#pragma unroll
            for (int m = 0; m < TM; m++) a2[m] = pk2(Xs[tr * TM + m][kk]);
#pragma unroll
            for (int p = 0; p < NP; p++)
                b2[p] = *(const unsigned long long*)&Ws[kk][tc * TN + 2 * p];
#pragma unroll
            for (int m = 0; m < TM; m++)
#pragma unroll
                for (int p = 0; p < NP; p++) fma2(acc[m][p], a2[m], b2[p]);
        }
        __syncthreads();
    }

#pragma unroll
    for (int m = 0; m < TM; m++) {
        int r = row0 + tr * TM + m;
        if (r < n) {
            float sc = SCALE ? scale[r] : 1.0f;
#pragma unroll
            for (int p = 0; p < NP; p++) {
                float2 f = up2(acc[m][p]);
                if (SCALE) { f.x *= sc; f.y *= sc; }
                __nv_bfloat162 b = __float22bfloat162_rn(f);
                *(__nv_bfloat162*)(Y + (size_t)r * D + tc * TN + 2 * p) = b;
            }
        }
    }
}

// ---------------- CSR gather, 128-wide: 16 lanes x 16B per edge -------------
__device__ __forceinline__ void accum8(float acc[8], uint4 v, float w) {
    float2 f;
    f = __bfloat1622float2(*(const __nv_bfloat162*)&v.x);
    acc[0] = fmaf(f.x, w, acc[0]); acc[1] = fmaf(f.y, w, acc[1]);
    f = __bfloat1622float2(*(const __nv_bfloat162*)&v.y);
    acc[2] = fmaf(f.x, w, acc[2]); acc[3] = fmaf(f.y, w, acc[3]);
    f = __bfloat1622float2(*(const __nv_bfloat162*)&v.z);
    acc[4] = fmaf(f.x, w, acc[4]); acc[5] = fmaf(f.y, w, acc[5]);
    f = __bfloat1622float2(*(const __nv_bfloat162*)&v.w);
    acc[6] = fmaf(f.x, w, acc[6]); acc[7] = fmaf(f.y, w, acc[7]);
}

template <bool RELU, bool SRCNORM>
__global__ void __launch_bounds__(256)
gather128_kernel(const __nv_bfloat16* __restrict__ Y, const float* __restrict__ ns,
                 const float* __restrict__ nd, const float* __restrict__ bias,
                 float* __restrict__ out, int node_base, int node_cnt) {
    int w = (blockIdx.x * blockDim.x + threadIdx.x) >> 5;
    if (w >= node_cnt) return;
    int node = node_base + w;
    int lane = threadIdx.x & 31;
    int half = lane >> 4;         // which edge of the pair this lane serves
    int colq = lane & 15;         // 16B chunk within the 256B row
    int beg = g_off[node], end = g_off[node + 1];

    float acc[8];
#pragma unroll
    for (int k = 0; k < 8; k++) acc[k] = 0.f;

    for (int base = beg; base < end; base += 32) {
        int t = base + lane;
        int sl = (t < end) ? g_csrc[t] : 0;
        int m = min(32, end - base);
        int j = 0;
        for (; j + 4 <= m; j += 4) {
            int sA = __shfl_sync(0xffffffffu, sl, j + half);
            int sB = __shfl_sync(0xffffffffu, sl, j + 2 + half);
            uint4 vA = *(const uint4*)(Y + (size_t)sA * 128 + colq * 8);
            uint4 vB = *(const uint4*)(Y + (size_t)sB * 128 + colq * 8);
            float wA = SRCNORM ? __ldg(&ns[sA]) : 1.0f;
            float wB = SRCNORM ? __ldg(&ns[sB]) : 1.0f;
            accum8(acc, vA, wA);
            accum8(acc, vB, wB);
        }
        for (; j + 2 <= m; j += 2) {
            int sA = __shfl_sync(0xffffffffu, sl, j + half);
            uint4 vA = *(const uint4*)(Y + (size_t)sA * 128 + colq * 8);
            float wA = SRCNORM ? __ldg(&ns[sA]) : 1.0f;
            accum8(acc, vA, wA);
        }
        if (j < m) {  // one leftover edge; only half 0 participates
            int sA = __shfl_sync(0xffffffffu, sl, j);
            if (half == 0) {
                uint4 vA = *(const uint4*)(Y + (size_t)sA * 128 + colq * 8);
                float wA = SRCNORM ? __ldg(&ns[sA]) : 1.0f;
                accum8(acc, vA, wA);
            }
        }
    }

    // merge the two halves
#pragma unroll
    for (int k = 0; k < 8; k++)
        acc[k] += __shfl_xor_sync(0xffffffffu, acc[k], 16);

    if (half == 0) {
        float ndv = nd[node];
        float4 b0 = *(const float4*)(bias + colq * 8);
        float4 b1 = *(const float4*)(bias + colq * 8 + 4);
        float4 r0, r1;
        r0.x = acc[0] * ndv + b0.x; r0.y = acc[1] * ndv + b0.y;
        r0.z = acc[2] * ndv + b0.z; r0.w = acc[3] * ndv + b0.w;
        r1.x = acc[4] * ndv + b1.x; r1.y = acc[5] * ndv + b1.y;
        r1.z = acc[6] * ndv + b1.z; r1.w = acc[7] * ndv + b1.w;
        if (RELU) {
            r0.x = fmaxf(r0.x, 0.f); r0.y = fmaxf(r0.y, 0.f);
            r0.z = fmaxf(r0.z, 0.f); r0.w = fmaxf(r0.w, 0.f);
            r1.x = fmaxf(r1.x, 0.f); r1.y = fmaxf(r1.y, 0.f);
            r1.z = fmaxf(r1.z, 0.f); r1.w = fmaxf(r1.w, 0.f);
        }
        *(float4*)(out + (size_t)node * 128 + colq * 8)     = r0;
        *(float4*)(out + (size_t)node * 128 + colq * 8 + 4) = r1;
    }
}

// ---------------- CSR gather, 64-wide: 8 lanes x 16B per edge ---------------
__global__ void __launch_bounds__(256)
gather64_kernel(const __nv_bfloat16* __restrict__ Y, const float* __restrict__ nd,
                const float* __restrict__ bias, float* __restrict__ out,
                int node_base, int node_cnt) {
    int w = (blockIdx.x * blockDim.x + threadIdx.x) >> 5;
    if (w >= node_cnt) return;
    int node = node_base + w;
    int lane = threadIdx.x & 31;
    int quarter = lane >> 3;      // which edge of the quad this lane serves
    int colq = lane & 7;          // 16B chunk within the 128B row
    int beg = g_off[node], end = g_off[node + 1];

    float acc[8];
#pragma unroll
    for (int k = 0; k < 8; k++) acc[k] = 0.f;

    for (int base = beg; base < end; base += 32) {
        int t = base + lane;
        int sl = (t < end) ? g_csrc[t] : 0;
        int m = min(32, end - base);
        int j = 0;
        for (; j + 8 <= m; j += 8) {
            int sA = __shfl_sync(0xffffffffu, sl, j + quarter);
            int sB = __shfl_sync(0xffffffffu, sl, j + 4 + quarter);
            uint4 vA = *(const uint4*)(Y + (size_t)sA * 64 + colq * 8);
            uint4 vB = *(const uint4*)(Y + (size_t)sB * 64 + colq * 8);
            accum8(acc, vA, 1.0f);
            accum8(acc, vB, 1.0f);
        }
        for (; j + 4 <= m; j += 4) {
            int sA = __shfl_sync(0xffffffffu, sl, j + quarter);
            uint4 vA = *(const uint4*)(Y + (size_t)sA * 64 + colq * 8);
            accum8(acc, vA, 1.0f);
        }
        if (j < m) {
            int rem = m - j;   // 1..3
            int idx = j + (quarter < rem ? quarter : 0);
            int sA = __shfl_sync(0xffffffffu, sl, idx);
            if (quarter < rem) {
                uint4 vA = *(const uint4*)(Y + (size_t)sA * 64 + colq * 8);
                accum8(acc, vA, 1.0f);
            }
        }
    }

    // merge quarters: xor 8 then xor 16
#pragma unroll
    for (int k = 0; k < 8; k++) {
        acc[k] += __shfl_xor_sync(0xffffffffu, acc[k], 8);
        acc[k] += __shfl_xor_sync(0xffffffffu, acc[k], 16);
    }

    if (quarter == 0) {
        float ndv = nd[node];
        float4 b0 = *(const float4*)(bias + colq * 8);
        float4 b1 = *(const float4*)(bias + colq * 8 + 4);
        float4 r0, r1;
        r0.x = acc[0] * ndv + b0.x; r0.y = acc[1] * ndv + b0.y;
        r0.z = acc[2] * ndv + b0.z; r0.w = acc[3] * ndv + b0.w;
        r1.x = acc[4] * ndv + b1.x; r1.y = acc[5] * ndv + b1.y;
        r1.z = acc[6] * ndv + b1.z; r1.w = acc[7] * ndv + b1.w;
        *(float4*)(out + (size_t)node * 64 + colq * 8)     = r0;
        *(float4*)(out + (size_t)node * 64 + colq * 8 + 4) = r1;
    }
}

// ---------------- host orchestration ----------------------------------------
extern "C" void kernel_launch(void* const* d_in, const int* in_sizes, int n_in,
                              void* d_out, int out_size) {
    const float* features = (const float*)d_in[0];
    const float* W1 = (const float*)d_in[1];
    const float* b1 = (const float*)d_in[2];
    const float* W2 = (const float*)d_in[3];
    const float* b2 = (const float*)d_in[4];
    const float* W3 = (const float*)d_in[5];
    const float* b3 = (const float*)d_in[6];
    const int*   src = (const int*)d_in[7];
    const int*   dst = (const int*)d_in[8];
    const int E = in_sizes[7];
    float* out = (float*)d_out;

    float *nrm_s, *nrm_d, *h;
    __nv_bfloat16 *ya, *yb;
    int *outdeg, *indeg;
    cudaGetSymbolAddress((void**)&nrm_s,  g_norm_src);
    cudaGetSymbolAddress((void**)&nrm_d,  g_norm_dst);
    cudaGetSymbolAddress((void**)&ya,     g_ya);
    cudaGetSymbolAddress((void**)&yb,     g_yb);
    cudaGetSymbolAddress((void**)&h,      g_h);
    cudaGetSymbolAddress((void**)&outdeg, g_outdeg);
    cudaGetSymbolAddress((void**)&indeg,  g_indeg);

    static cudaStream_t s2 = nullptr;
    static cudaEvent_t evFork = nullptr, evJoin = nullptr;
    static cudaEvent_t evA = nullptr, evB = nullptr, evC = nullptr, evD = nullptr;
    if (s2 == nullptr) {
        cudaStreamCreateWithFlags(&s2, cudaStreamNonBlocking);
        cudaEventCreateWithFlags(&evFork, cudaEventDisableTiming);
        cudaEventCreateWithFlags(&evJoin, cudaEventDisableTiming);
        cudaEventCreateWithFlags(&evA, cudaEventDisableTiming);
        cudaEventCreateWithFlags(&evB, cudaEventDisableTiming);
        cudaEventCreateWithFlags(&evC, cudaEventDisableTiming);
        cudaEventCreateWithFlags(&evD, cudaEventDisableTiming);
    }

    const int TPB = 256;
    const int nchunk = (NN + 255) / 256;        // 196
    const int gemm_blocks_full = (NN + 63) / 64;
    const int NH = NN / 2;                      // 25000
    const int gemm_blocks_half = (NH + 63) / 64;
    const int gath_half = (NH * 32 + TPB - 1) / TPB;
    const int gath_full = (NN * 32 + TPB - 1) / TPB;

    // fork: GEMM-1 (inputs only) overlaps the CSR build
    cudaEventRecord(evFork, 0);
    cudaStreamWaitEvent(s2, evFork, 0);
    gemm_kernel<128, false><<<gemm_blocks_full, 256, 0, s2>>>(features, W1, nullptr, ya, NN);
    cudaEventRecord(evJoin, s2);

    zero_int2<<<(NN + TPB - 1) / TPB, TPB>>>(outdeg, indeg, NN);
    deg_kernel<<<(E + TPB - 1) / TPB, TPB>>>(src, dst, E);
    scan_sum_kernel<<<nchunk, 256>>>();
    scan_apply_kernel<<<nchunk, 256>>>(nchunk, E);
    fill_kernel<<<(E + TPB - 1) / TPB, TPB>>>(src, dst, E);
    cudaStreamWaitEvent(0, evJoin, 0);

    // --- layer 1 gather (norm_src applied per-edge), pipelined with gemm2 ---
    gather128_kernel<true, true><<<gath_half, TPB>>>(ya, nrm_s, nrm_d, b1, h, 0, NH);
    cudaEventRecord(evA, 0);
    gather128_kernel<true, true><<<gath_half, TPB>>>(ya, nrm_s, nrm_d, b1, h, NH, NN - NH);

    cudaStreamWaitEvent(s2, evA, 0);
    gemm_kernel<128, true><<<gemm_blocks_half, 256, 0, s2>>>(h, W2, nrm_s, yb, NH);
    cudaEventRecord(evB, s2);
    gemm_kernel<128, true><<<gemm_blocks_half, 256>>>(h + (size_t)NH * 128, W2, nrm_s + NH,
                                                      yb + (size_t)NH * 128, NN - NH);
    cudaStreamWaitEvent(0, evB, 0);

    // --- layer 2 gather, pipelined with gemm3 ---
    gather128_kernel<true, false><<<gath_half, TPB>>>(yb, nullptr, nrm_d, b2, h, 0, NH);
    cudaEventRecord(evC, 0);
    gather128_kernel<true, false><<<gath_half, TPB>>>(yb, nullptr, nrm_d, b2, h, NH, NN - NH);

    cudaStreamWaitEvent(s2, evC, 0);
    gemm_kernel<64, true><<<gemm_blocks_half, 256, 0, s2>>>(h, W3, nrm_s, ya, NH);
    cudaEventRecord(evD, s2);
    gemm_kernel<64, true><<<gemm_blocks_half, 256>>>(h + (size_t)NH * 128, W3, nrm_s + NH,
                                                     ya + (size_t)NH * 64, NN - NH);
    cudaStreamWaitEvent(0, evD, 0);

    // --- layer 3 gather ---
    gather64_kernel<<<gath_full, TPB>>>(ya, nrm_d, b3, out, 0, NN);
}

// round 6
// speedup vs baseline: 1.2604x; 1.2604x over previous
#include <cuda_runtime.h>
#include <cuda_bf16.h>
#include <cstdint>

#define NN 50000
#define KD 128
#define EMAX 1000000

// ---------------- scratch (device globals; no allocation allowed) ----------
__device__ int   g_outdeg[NN];
__device__ int   g_indeg[NN];
__device__ float g_norm_src[NN];
__device__ float g_norm_dst[NN];
__device__ int   g_off[NN + 1];
__device__ int   g_cursor[NN];
__device__ int   g_chunk_sum[256];
__device__ int   g_csrc[EMAX];
__device__ __nv_bfloat16 g_y[(size_t)NN * 128];
__device__ float g_h[(size_t)NN * 128];

__device__ __forceinline__ uint32_t smem_u32(const void* p) {
    uint32_t a;
    asm("{ .reg .u64 t; cvta.to.shared.u64 t, %1; cvt.u32.u64 %0, t; }" : "=r"(a) : "l"(p));
    return a;
}

// ---------------- tiny setup kernels ----------------------------------------
__global__ void zero_int2(int* a, int* b, int n) {
    int i = blockIdx.x * blockDim.x + threadIdx.x;
    if (i < n) { a[i] = 0; b[i] = 0; }
}

__global__ void deg_kernel(const int* __restrict__ src, const int* __restrict__ dst, int E) {
    int i = blockIdx.x * blockDim.x + threadIdx.x;
    if (i < E) {
        atomicAdd(&g_outdeg[src[i]], 1);
        atomicAdd(&g_indeg[dst[i]], 1);
    }
}

__global__ void scan_sum_kernel() {
    __shared__ int s[256];
    int t = threadIdx.x;
    int idx = blockIdx.x * 256 + t;
    int v = (idx < NN) ? g_indeg[idx] : 0;
    s[t] = v; __syncthreads();
    for (int o = 128; o > 0; o >>= 1) {
        if (t < o) s[t] += s[t + o];
        __syncthreads();
    }
    if (t == 0) g_chunk_sum[blockIdx.x] = s[0];
}

__global__ void scan_apply_kernel(int nchunk, int E) {
    __shared__ int cs[256];
    __shared__ int s[256];
    int t = threadIdx.x;
    int cv = (t < nchunk) ? g_chunk_sum[t] : 0;
    cs[t] = cv; __syncthreads();
    for (int o = 1; o < 256; o <<= 1) {
        int x = (t >= o) ? cs[t - o] : 0;
        __syncthreads();
        cs[t] += x;
        __syncthreads();
    }
    int base = (blockIdx.x == 0) ? 0 : cs[blockIdx.x - 1];

    int idx = blockIdx.x * 256 + t;
    int v = (idx < NN) ? g_indeg[idx] : 0;
    s[t] = v; __syncthreads();
    for (int o = 1; o < 256; o <<= 1) {
        int x = (t >= o) ? s[t - o] : 0;
        __syncthreads();
        s[t] += x;
        __syncthreads();
    }
    if (idx < NN) {
        int excl = base + s[t] - v;
        g_off[idx] = excl;
        g_cursor[idx] = excl;
        g_norm_src[idx] = rsqrtf(fmaxf((float)g_outdeg[idx], 1.0f));
        g_norm_dst[idx] = rsqrtf(fmaxf((float)v, 1.0f));
    }
    if (idx == 0) g_off[NN] = E;
}

__global__ void fill_kernel(const int* __restrict__ src, const int* __restrict__ dst, int E) {
    int e = blockIdx.x * blockDim.x + threadIdx.x;
    if (e < E) {
        int pos = atomicAdd(&g_cursor[dst[e]], 1);
        g_csrc[pos] = src[e];
    }
}

// ---------------- split-bf16 HMMA GEMM (mma.sync m16n8k16) ------------------
// Y[i,0:N] = [scale[i]] * (X[i,0:128] @ W[0:128,0:N]) with near-fp32 accuracy:
// D = Ah*Bh + Al*Bh + Ah*Bl (bf16 hi/lo split, lo*lo dropped).
// CTA: 64 rows x N cols, 256 threads = 8 warps (2 m x 4 n).
template <int N, bool SCALE>
__global__ void __launch_bounds__(256)
hmma_gemm_kernel(const float* __restrict__ X, const float* __restrict__ W,
                 const float* __restrict__ scale, __nv_bfloat16* __restrict__ Y, int n) {
    constexpr int BM = 64;
    constexpr int AST = 136;                 // padded bf16 stride (272B)
    constexpr int WARP_N = N / 4;            // 32 (N=128) / 16 (N=64)
    constexpr int NT = WARP_N / 8;           // n-tiles per warp: 4 / 2

    extern __shared__ __nv_bfloat16 sm[];
    __nv_bfloat16* sAh = sm;
    __nv_bfloat16* sAl = sm + BM * AST;
    __nv_bfloat16* sBh = sm + 2 * BM * AST;
    __nv_bfloat16* sBl = sm + 2 * BM * AST + N * AST;

    const int tid  = threadIdx.x;
    const int wid  = tid >> 5;
    const int lane = tid & 31;
    const int row0 = blockIdx.x * BM;

    // ---- stage A (X rows, hi/lo split) ----
#pragma unroll
    for (int i = 0; i < 8; i++) {
        int fq = tid + i * 256;              // 2048 float4s: 64 rows x 32
        int r  = fq >> 5;
        int q  = fq & 31;
        float4 v = make_float4(0.f, 0.f, 0.f, 0.f);
        if (row0 + r < n)
            v = *(const float4*)(X + (size_t)(row0 + r) * KD + q * 4);
        __nv_bfloat16 hx = __float2bfloat16(v.x), hy = __float2bfloat16(v.y);
        __nv_bfloat16 hz = __float2bfloat16(v.z), hw = __float2bfloat16(v.w);
        __nv_bfloat162 h0; h0.x = hx; h0.y = hy;
        __nv_bfloat162 h1; h1.x = hz; h1.y = hw;
        __nv_bfloat162 l0, l1;
        l0.x = __float2bfloat16(v.x - __bfloat162float(hx));
        l0.y = __float2bfloat16(v.y - __bfloat162float(hy));
        l1.x = __float2bfloat16(v.z - __bfloat162float(hz));
        l1.y = __float2bfloat16(v.w - __bfloat162float(hw));
        *(__nv_bfloat162*)(sAh + r * AST + q * 4)     = h0;
        *(__nv_bfloat162*)(sAh + r * AST + q * 4 + 2) = h1;
        *(__nv_bfloat162*)(sAl + r * AST + q * 4)     = l0;
        *(__nv_bfloat162*)(sAl + r * AST + q * 4 + 2) = l1;
    }

    // ---- stage B = W^T (N rows x 128 cols), hi/lo split ----
#pragma unroll
    for (int i = 0; i < (KD * N) / 256; i++) {
        int idx = tid + i * 256;
        int k  = idx / N;
        int nn = idx % N;
        float w = W[(size_t)k * N + nn];
        __nv_bfloat16 hi = __float2bfloat16(w);
        sBh[nn * AST + k] = hi;
        sBl[nn * AST + k] = __float2bfloat16(w - __bfloat162float(hi));
    }
    __syncthreads();

    const uint32_t base_u32 = smem_u32(sm);
    const uint32_t aHi = base_u32;
    const uint32_t aLo = base_u32 + BM * AST * 2;
    const uint32_t bHi = base_u32 + 2 * BM * AST * 2;
    const uint32_t bLo = bHi + N * AST * 2;

    const int wm = wid >> 2;                 // 0..1
    const int wn = wid & 3;                  // 0..3
    const int m_base = wm * 32;
    const int n_base = wn * WARP_N;

    // precompute per-lane ldmatrix address offsets (element units)
    const int a_tile = lane >> 3, a_row = lane & 7;
    const int aoff_r = (a_tile & 1) * 8 + a_row;     // row within 16-row block
    const int aoff_c = (a_tile >> 1) * 8;            // col half
    const int b_row = lane & 7;
    const int boff_c = ((lane >> 3) & 1) * 8;

    float c[2][NT][4];
#pragma unroll
    for (int mt = 0; mt < 2; mt++)
#pragma unroll
        for (int nt = 0; nt < NT; nt++)
#pragma unroll
            for (int q = 0; q < 4; q++) c[mt][nt][q] = 0.f;

#pragma unroll
    for (int ks = 0; ks < 24; ks++) {
        const int pass = ks >> 3;
        const int kcol = (ks & 7) * 16;
        const uint32_t aB = (pass == 1) ? aLo : aHi;
        const uint32_t bB = (pass == 2) ? bLo : bHi;

        uint32_t a[2][4];
#pragma unroll
        for (int mt = 0; mt < 2; mt++) {
            uint32_t addr = aB + ((m_base + mt * 16 + aoff_r) * AST + kcol + aoff_c) * 2;
            asm volatile("ldmatrix.sync.aligned.m8n8.x4.shared.b16 {%0,%1,%2,%3}, [%4];"
                         : "=r"(a[mt][0]), "=r"(a[mt][1]), "=r"(a[mt][2]), "=r"(a[mt][3])
                         : "r"(addr));
        }
        uint32_t b[NT][2];
#pragma unroll
        for (int nt = 0; nt < NT; nt++) {
            uint32_t addr = bB + ((n_base + nt * 8 + b_row) * AST + kcol + boff_c) * 2;
            asm volatile("ldmatrix.sync.aligned.m8n8.x2.shared.b16 {%0,%1}, [%2];"
                         : "=r"(b[nt][0]), "=r"(b[nt][1]) : "r"(addr));
        }
#pragma unroll
        for (int mt = 0; mt < 2; mt++)
#pragma unroll
            for (int nt = 0; nt < NT; nt++) {
                asm volatile(
                    "mma.sync.aligned.m16n8k16.row.col.f32.bf16.bf16.f32 "
                    "{%0,%1,%2,%3}, {%4,%5,%6,%7}, {%8,%9}, {%0,%1,%2,%3};"
                    : "+f"(c[mt][nt][0]), "+f"(c[mt][nt][1]),
                      "+f"(c[mt][nt][2]), "+f"(c[mt][nt][3])
                    : "r"(a[mt][0]), "r"(a[mt][1]), "r"(a[mt][2]), "r"(a[mt][3]),
                      "r"(b[nt][0]), "r"(b[nt][1]));
            }
    }

    // ---- epilogue: scale + bf16 store ----
#pragma unroll
    for (int mt = 0; mt < 2; mt++) {
        int r0 = row0 + m_base + mt * 16 + (lane >> 2);
        int r1 = r0 + 8;
        float sc0 = 1.0f, sc1 = 1.0f;
        if (SCALE) {
            if (r0 < n) sc0 = scale[r0];
            if (r1 < n) sc1 = scale[r1];
        }
        int ncol = n_base + (lane & 3) * 2;
#pragma unroll
        for (int nt = 0; nt < NT; nt++) {
            if (r0 < n) {
                float2 f; f.x = c[mt][nt][0] * sc0; f.y = c[mt][nt][1] * sc0;
                __nv_bfloat162 bb = __float22bfloat162_rn(f);
                *(__nv_bfloat162*)(Y + (size_t)r0 * N + ncol + nt * 8) = bb;
            }
            if (r1 < n) {
                float2 f; f.x = c[mt][nt][2] * sc1; f.y = c[mt][nt][3] * sc1;
                __nv_bfloat162 bb = __float22bfloat162_rn(f);
                *(__nv_bfloat162*)(Y + (size_t)r1 * N + ncol + nt * 8) = bb;
            }
        }
    }
}

// ---------------- CSR gather-aggregate (bf16 in, fp32 accum) ----------------
template <bool RELU, bool SRCNORM>
__global__ void __launch_bounds__(256)
gather128_kernel(const __nv_bfloat16* __restrict__ Y, const float* __restrict__ ns,
                 const float* __restrict__ nd, const float* __restrict__ bias,
                 float* __restrict__ out) {
    int warp = (blockIdx.x * blockDim.x + threadIdx.x) >> 5;
    int lane = threadIdx.x & 31;
    if (warp >= NN) return;
    int beg = g_off[warp];
    int end = g_off[warp + 1];
    float4 acc0 = make_float4(0.f, 0.f, 0.f, 0.f);
    float4 acc1 = make_float4(0.f, 0.f, 0.f, 0.f);
    for (int base = beg; base < end; base += 32) {
        int t = base + lane;
        int sl = (t < end) ? g_csrc[t] : 0;
        int m = min(32, end - base);
        int j = 0;
        for (; j + 1 < m; j += 2) {
            int s0 = __shfl_sync(0xffffffff, sl, j);
            int s1 = __shfl_sync(0xffffffff, sl, j + 1);
            uint2 u0 = *(const uint2*)(Y + (size_t)s0 * 128 + lane * 4);
            uint2 u1 = *(const uint2*)(Y + (size_t)s1 * 128 + lane * 4);
            float2 a0 = __bfloat1622float2(*(const __nv_bfloat162*)&u0.x);
            float2 a1 = __bfloat1622float2(*(const __nv_bfloat162*)&u0.y);
            float2 c0 = __bfloat1622float2(*(const __nv_bfloat162*)&u1.x);
            float2 c1 = __bfloat1622float2(*(const __nv_bfloat162*)&u1.y);
            if (SRCNORM) {
                float w0 = __ldg(&ns[s0]);
                float w1 = __ldg(&ns[s1]);
                acc0.x += a0.x * w0; acc0.y += a0.y * w0;
                acc0.z += a1.x * w0; acc0.w += a1.y * w0;
                acc1.x += c0.x * w1; acc1.y += c0.y * w1;
                acc1.z += c1.x * w1; acc1.w += c1.y * w1;
            } else {
                acc0.x += a0.x; acc0.y += a0.y; acc0.z += a1.x; acc0.w += a1.y;
                acc1.x += c0.x; acc1.y += c0.y; acc1.z += c1.x; acc1.w += c1.y;
            }
        }
        if (j < m) {
            int s0 = __shfl_sync(0xffffffff, sl, j);
            uint2 u0 = *(const uint2*)(Y + (size_t)s0 * 128 + lane * 4);
            float2 a0 = __bfloat1622float2(*(const __nv_bfloat162*)&u0.x);
            float2 a1 = __bfloat1622float2(*(const __nv_bfloat162*)&u0.y);
            float w0 = SRCNORM ? __ldg(&ns[s0]) : 1.0f;
            acc0.x += a0.x * w0; acc0.y += a0.y * w0;
            acc0.z += a1.x * w0; acc0.w += a1.y * w0;
        }
    }
    float ndv = nd[warp];
    float4 bb = *(const float4*)(bias + lane * 4);
    float4 r;
    r.x = (acc0.x + acc1.x) * ndv + bb.x;
    r.y = (acc0.y + acc1.y) * ndv + bb.y;
    r.z = (acc0.z + acc1.z) * ndv + bb.z;
    r.w = (acc0.w + acc1.w) * ndv + bb.w;
    if (RELU) {
        r.x = fmaxf(r.x, 0.f); r.y = fmaxf(r.y, 0.f);
        r.z = fmaxf(r.z, 0.f); r.w = fmaxf(r.w, 0.f);
    }
    *(float4*)(out + (size_t)warp * 128 + lane * 4) = r;
}

__global__ void __launch_bounds__(256)
gather64_kernel(const __nv_bfloat16* __restrict__ Y, const float* __restrict__ nd,
                const float* __restrict__ bias, float* __restrict__ out) {
    int warp = (blockIdx.x * blockDim.x + threadIdx.x) >> 5;
    int lane = threadIdx.x & 31;
    if (warp >= NN) return;
    int beg = g_off[warp];
    int end = g_off[warp + 1];
    float2 acc0 = make_float2(0.f, 0.f);
    float2 acc1 = make_float2(0.f, 0.f);
    for (int base = beg; base < end; base += 32) {
        int t = base + lane;
        int sl = (t < end) ? g_csrc[t] : 0;
        int m = min(32, end - base);
        int j = 0;
        for (; j + 1 < m; j += 2) {
            int s0 = __shfl_sync(0xffffffff, sl, j);
            int s1 = __shfl_sync(0xffffffff, sl, j + 1);
            unsigned u0 = *(const unsigned*)(Y + (size_t)s0 * 64 + lane * 2);
            unsigned u1 = *(const unsigned*)(Y + (size_t)s1 * 64 + lane * 2);
            float2 a0 = __bfloat1622float2(*(const __nv_bfloat162*)&u0);
            float2 a1 = __bfloat1622float2(*(const __nv_bfloat162*)&u1);
            acc0.x += a0.x; acc0.y += a0.y;
            acc1.x += a1.x; acc1.y += a1.y;
        }
        if (j < m) {
            int s0 = __shfl_sync(0xffffffff, sl, j);
            unsigned u0 = *(const unsigned*)(Y + (size_t)s0 * 64 + lane * 2);
            float2 a0 = __bfloat1622float2(*(const __nv_bfloat162*)&u0);
            acc0.x += a0.x; acc0.y += a0.y;
        }
    }
    float ndv = nd[warp];
    float2 bb = *(const float2*)(bias + lane * 2);
    float2 r;
    r.x = (acc0.x + acc1.x) * ndv + bb.x;
    r.y = (acc0.y + acc1.y) * ndv + bb.y;
    *(float2*)(out + (size_t)warp * 64 + lane * 2) = r;
}

// ---------------- host orchestration ----------------------------------------
extern "C" void kernel_launch(void* const* d_in, const int* in_sizes, int n_in,
                              void* d_out, int out_size) {
    const float* features = (const float*)d_in[0];
    const float* W1 = (const float*)d_in[1];
    const float* b1 = (const float*)d_in[2];
    const float* W2 = (const float*)d_in[3];
    const float* b2 = (const float*)d_in[4];
    const float* W3 = (const float*)d_in[5];
    const float* b3 = (const float*)d_in[6];
    const int*   src = (const int*)d_in[7];
    const int*   dst = (const int*)d_in[8];
    const int E = in_sizes[7];
    float* out = (float*)d_out;

    float *nrm_s, *nrm_d, *h;
    __nv_bfloat16* y;
    int *outdeg, *indeg;
    cudaGetSymbolAddress((void**)&nrm_s,  g_norm_src);
    cudaGetSymbolAddress((void**)&nrm_d,  g_norm_dst);
    cudaGetSymbolAddress((void**)&y,      g_y);
    cudaGetSymbolAddress((void**)&h,      g_h);
    cudaGetSymbolAddress((void**)&outdeg, g_outdeg);
    cudaGetSymbolAddress((void**)&indeg,  g_indeg);

    // smem: (2*64 + 2*N) * 136 * 2 bytes
    const int SMEM128 = (2 * 64 + 2 * 128) * 136 * 2;  // 104448
    const int SMEM64  = (2 * 64 + 2 * 64) * 136 * 2;   // 69632

    static cudaStream_t s2 = nullptr;
    static cudaEvent_t evFork = nullptr, evJoin = nullptr;
    if (s2 == nullptr) {
        cudaStreamCreateWithFlags(&s2, cudaStreamNonBlocking);
        cudaEventCreateWithFlags(&evFork, cudaEventDisableTiming);
        cudaEventCreateWithFlags(&evJoin, cudaEventDisableTiming);
        cudaFuncSetAttribute(hmma_gemm_kernel<128, false>,
                             cudaFuncAttributeMaxDynamicSharedMemorySize, SMEM128);
        cudaFuncSetAttribute(hmma_gemm_kernel<128, true>,
                             cudaFuncAttributeMaxDynamicSharedMemorySize, SMEM128);
        cudaFuncSetAttribute(hmma_gemm_kernel<64, true>,
                             cudaFuncAttributeMaxDynamicSharedMemorySize, SMEM64);
    }

    const int TPB = 256;
    const int nchunk = (NN + 255) / 256;       // 196
    const int gemm_blocks = (NN + 63) / 64;    // 782
    const int gather_blocks = (NN * 32 + TPB - 1) / TPB;

    // fork: GEMM-1 (inputs only) overlaps the CSR build
    cudaEventRecord(evFork, 0);
    cudaStreamWaitEvent(s2, evFork, 0);
    hmma_gemm_kernel<128, false><<<gemm_blocks, 256, SMEM128, s2>>>(features, W1, nullptr, y, NN);
    cudaEventRecord(evJoin, s2);

    zero_int2<<<(NN + TPB - 1) / TPB, TPB>>>(outdeg, indeg, NN);
    deg_kernel<<<(E + TPB - 1) / TPB, TPB>>>(src, dst, E);
    scan_sum_kernel<<<nchunk, 256>>>();
    scan_apply_kernel<<<nchunk, 256>>>(nchunk, E);
    fill_kernel<<<(E + TPB - 1) / TPB, TPB>>>(src, dst, E);
    cudaStreamWaitEvent(0, evJoin, 0);

    // --- layer 1: gather applies norm_src per-edge (GEMM-1 ran unscaled) ---
    gather128_kernel<true, true><<<gather_blocks, TPB>>>(y, nrm_s, nrm_d, b1, h);

    // --- layer 2 ---
    hmma_gemm_kernel<128, true><<<gemm_blocks, 256, SMEM128>>>(h, W2, nrm_s, y, NN);
    gather128_kernel<true, false><<<gather_blocks, TPB>>>(y, nullptr, nrm_d, b2, h);

    // --- layer 3 ---
    hmma_gemm_kernel<64, true><<<gemm_blocks, 256, SMEM64>>>(h, W3, nrm_s, y, NN);
    gather64_kernel<<<gather_blocks, TPB>>>(y, nrm_d, b3, out);
}